// round 12
// baseline (speedup 1.0000x reference)
#include <cuda_runtime.h>
#include <math.h>

#define Hpix 512
#define Wpix 512
#define EPSF 1e-8f
#define BIGF 1e30f
#define MAXN 4
#define MAXV 8192
#define MAXF 8192
#define TW 32
#define TH 16
#define TCH  256
#define NB   64
#define CULL_MARGIN 8.0f

// ---- scratch (static device globals: no allocations allowed) ----
__device__ float  g_vpix[MAXN * MAXV * 3];
// unsorted (setup output)
__device__ float4 g_B [MAXN * MAXF];
__device__ float4 g_F0[MAXN * MAXF];
__device__ float4 g_F1[MAXN * MAXF];
__device__ float4 g_F2[MAXN * MAXF];
__device__ float4 g_F3[MAXN * MAXF];
__device__ float4 g_F4[MAXN * MAXF];
__device__ float  g_minz[MAXN * MAXF];
__device__ int    g_bucket[MAXN * MAXF];
// sorted (scatter output)
__device__ float4 s_B [MAXN * MAXF];
__device__ float4 s_F0[MAXN * MAXF];
__device__ float4 s_F1[MAXN * MAXF];
__device__ float4 s_F2[MAXN * MAXF];
__device__ float4 s_F3[MAXN * MAXF];
__device__ float4 s_F4[MAXN * MAXF];
__device__ float  s_sz[MAXN * MAXF];   // min vertex z (clamped) per sorted candidate
__device__ float  s_bf[MAXN * MAXF];   // conservative bucket floor (nondecreasing)
// sort bookkeeping (reset by memset nodes each launch)
__device__ int      g_hist  [MAXN * NB];
__device__ int      g_cursor[MAXN * NB];
__device__ unsigned g_zmin[MAXN];   // monotone-encoded min vertex z (init 0xFFFFFFFF)
__device__ unsigned g_zmax[MAXN];   // monotone-encoded max vertex z (init 0)

// monotone float<->uint mapping (works for any sign)
__device__ __forceinline__ unsigned fkey(float f) {
    unsigned b = __float_as_uint(f);
    return (b & 0x80000000u) ? ~b : (b | 0x80000000u);
}
__device__ __forceinline__ float funkey(unsigned u) {
    return (u & 0x80000000u) ? __uint_as_float(u ^ 0x80000000u)
                             : __uint_as_float(~u);
}

// edge function exactly as XLA:GPU contracts it: (a*b - c*d) -> fma(a,b,-(c*d))
__device__ __forceinline__ float edge_fn(float a, float b, float c, float d) {
    return __fmaf_rn(a, b, -__fmul_rn(c, d));
}

// ----------------------------------------------------------------
// Kernel 1: project vertices -> v_pix (bitwise-exact for identity cam)
// ----------------------------------------------------------------
__global__ void project_kernel(const float* __restrict__ v,
                               const float* __restrict__ campos,
                               const float* __restrict__ camrot,
                               const float* __restrict__ focal,
                               const float* __restrict__ princpt,
                               int N, int V)
{
    int idx = blockIdx.x * blockDim.x + threadIdx.x;
    if (idx >= N * V) return;
    int n = idx / V;
    const float* vv = v + (size_t)idx * 3;
    float dx = __fsub_rn(vv[0], campos[n*3+0]);
    float dy = __fsub_rn(vv[1], campos[n*3+1]);
    float dz = __fsub_rn(vv[2], campos[n*3+2]);
    const float* R = camrot + n*9;
    float c0 = __fadd_rn(__fadd_rn(__fmul_rn(R[0],dx), __fmul_rn(R[1],dy)), __fmul_rn(R[2],dz));
    float c1 = __fadd_rn(__fadd_rn(__fmul_rn(R[3],dx), __fmul_rn(R[4],dy)), __fmul_rn(R[5],dz));
    float c2 = __fadd_rn(__fadd_rn(__fmul_rn(R[6],dx), __fmul_rn(R[7],dy)), __fmul_rn(R[8],dz));
    float z  = fmaxf(c2, EPSF);
    float u  = __fdiv_rn(c0, z);
    float w  = __fdiv_rn(c1, z);
    const float* Fm = focal + n*4;
    float X = __fadd_rn(__fadd_rn(__fmul_rn(Fm[0],u), __fmul_rn(Fm[1],w)), princpt[n*2+0]);
    float Y = __fadd_rn(__fadd_rn(__fmul_rn(Fm[2],u), __fmul_rn(Fm[3],w)), princpt[n*2+1]);
    g_vpix[(size_t)idx*3+0] = X;
    g_vpix[(size_t)idx*3+1] = Y;
    g_vpix[(size_t)idx*3+2] = c2;
    float zc = fmaxf(c2, EPSF);
    atomicMin(&g_zmin[n], fkey(zc));
    atomicMax(&g_zmax[n], fkey(zc));
}

// ----------------------------------------------------------------
// Kernel 2: per-(view, triangle) setup with sign-flipped edges
// ----------------------------------------------------------------
__global__ void setup_kernel(const int* __restrict__ vi, int N, int V, int F)
{
    int idx = blockIdx.x * blockDim.x + threadIdx.x;
    if (idx >= N * F) return;
    int n = idx / F, f = idx - n * F;
    const float* vp = g_vpix + (size_t)n * V * 3;
    int i0 = vi[f*3+0]*3, i1 = vi[f*3+1]*3, i2 = vi[f*3+2]*3;
    float x0 = vp[i0], y0 = vp[i0+1], z0 = vp[i0+2];
    float x1 = vp[i1], y1 = vp[i1+1], z1 = vp[i1+2];
    float x2 = vp[i2], y2 = vp[i2+1], z2 = vp[i2+2];

    float dy21 = __fsub_rn(y2,y1), dx21 = __fsub_rn(x2,x1);
    float dy02 = __fsub_rn(y0,y2), dx02 = __fsub_rn(x0,x2);
    float dy10 = __fsub_rn(y1,y0), dx10 = __fsub_rn(x1,x0);
    float area = edge_fn(__fsub_rn(x2,x0), dy10, __fsub_rn(y2,y0), dx10);
    float z0m = fmaxf(z0, EPSF), z1m = fmaxf(z1, EPSF), z2m = fmaxf(z2, EPSF);
    bool valid = (fabsf(area) > EPSF) && (z0 > EPSF) && (z1 > EPSF) && (z2 > EPSF);

    float s = (area > 0.0f) ? 1.0f : -1.0f;   // exact sign flip
    float areaf = s*area;                     // |area|

    float R0 = __frcp_rn(__fmul_rn(areaf, z0m));
    float R1 = __frcp_rn(__fmul_rn(areaf, z1m));
    float R2 = __frcp_rn(__fmul_rn(areaf, z2m));

    float xmn, xmx, ymn, ymx;
    if (valid) {
        xmn = fminf(fminf(x0,x1),x2) - 1.0f;
        xmx = fmaxf(fmaxf(x0,x1),x2) + 1.0f;
        ymn = fminf(fminf(y0,y1),y2) - 1.0f;
        ymx = fmaxf(fmaxf(y0,y1),y2) + 1.0f;
    } else {
        xmn = BIGF; xmx = -BIGF; ymn = BIGF; ymx = -BIGF;
    }
    g_B [idx] = make_float4(xmn, xmx, ymn, ymx);
    g_F0[idx] = make_float4(x0, y0, x1, y1);
    g_F1[idx] = make_float4(x2, y2, s*dy21, s*dx21);
    g_F2[idx] = make_float4(s*dy02, s*dx02, s*dy10, s*dx10);
    g_F3[idx] = make_float4(areaf, R0, R1, R2);
    g_F4[idx] = make_float4(z0m, z1m, z2m, __int_as_float(f));

    // bucket by min vertex z
    float minz = fminf(fminf(z0m, z1m), z2m);
    float zlo = funkey(g_zmin[n]);
    float zhi = funkey(g_zmax[n]);
    float range = zhi - zlo;
    int b;
    if (range > 1e-6f) {
        b = (int)((minz - zlo) * ((float)NB / range));
        b = min(max(b, 0), NB - 1);
    } else b = 0;
    g_minz[idx] = minz;
    g_bucket[idx] = b;
    atomicAdd(&g_hist[n*NB + b], 1);
}

// ----------------------------------------------------------------
// Kernel 3: scatter triangles into bucket-sorted order (full payload).
// Exclusive bucket prefix computed inline (<=63 L2-hot loads).
// ----------------------------------------------------------------
__global__ void scatter_kernel(int N, int F)
{
    int idx = blockIdx.x * blockDim.x + threadIdx.x;
    if (idx >= N * F) return;
    int n = idx / F;
    int b = g_bucket[idx];
    int off = 0;
    for (int k = 0; k < b; k++) off += g_hist[n*NB + k];
    int slot = off + atomicAdd(&g_cursor[n*NB + b], 1);
    int dst = n * F + slot;
    s_B [dst] = g_B [idx];
    s_F0[dst] = g_F0[idx];
    s_F1[dst] = g_F1[idx];
    s_F2[dst] = g_F2[idx];
    s_F3[dst] = g_F3[idx];
    s_F4[dst] = g_F4[idx];
    s_sz[dst] = g_minz[idx];
    float zlo = funkey(g_zmin[n]);
    float zhi = funkey(g_zmax[n]);
    // conservative under-estimate of the bucket's lower z bound
    float bf = __fmaf_rn((float)b, (zhi - zlo) * (1.0f / NB), zlo);
    s_bf[dst] = bf * 0.9999f - 1e-6f;
}

// ----------------------------------------------------------------
// Kernel 4: 32x16 tiles, 2 pixels/thread, edge-cull compaction,
// z-skip + mid-chunk (every 32) and chunk-level block early break.
// ----------------------------------------------------------------
__global__ void __launch_bounds__(256)
raster_kernel(const int* __restrict__ vi, const int* __restrict__ vti,
              const float* __restrict__ vt, const float* __restrict__ tex,
              float* __restrict__ out, int N, int V, int F, int Ht, int Wt)
{
    __shared__ float4 sF0[TCH], sF1[TCH], sF2[TCH], sF3[TCH], sF4[TCH];
    __shared__ float  sZ[TCH], sFl[TCH];
    __shared__ int sWcnt[8];

    int n = blockIdx.z;
    int tx0 = blockIdx.x * TW, ty0 = blockIdx.y * TH;
    int wxA = tx0 + threadIdx.x;
    int wxB = wxA + 16;
    int hy  = ty0 + threadIdx.y;
    float pxA = (float)wxA, pxB = (float)wxB, py = (float)hy;
    float tXlo = (float)tx0, tXhi = (float)(tx0 + TW - 1);
    float tYlo = (float)ty0, tYhi = (float)(ty0 + TH - 1);
    int t = threadIdx.y * 16 + threadIdx.x;
    int lane = t & 31, wrp = t >> 5;
    size_t triBase = (size_t)n * F;

    float best_d[2]  = {BIGF, BIGF};
    float best_zi[2] = {0.0f, 0.0f};
    int   best_i[2]  = {-1, -1};
    float bd_bound = BIGF;   // max(best_d)*(1+1e-4), candidate skip threshold

    const float EW = (float)(TW - 1), EH = (float)(TH - 1);
    bool finished = false;

    for (int base = 0; base < F && !finished; base += TCH) {
        int f = base + t;
        bool pass = false;
        float4 c0, c1, c2, c3;
        if (f < F) {
            float4 bb = s_B[triBase + f];
            pass = (bb.y >= tXlo) && (bb.x <= tXhi) && (bb.w >= tYlo) && (bb.z <= tYhi);
            if (pass) {
                c0 = s_F0[triBase + f];
                c1 = s_F1[triBase + f];
                c2 = s_F2[triBase + f];
                c3 = s_F3[triBase + f];
                {
                    float b0 = (tXlo - c0.z) * c1.z - (tYlo - c0.w) * c1.w;
                    float mx = b0 + fmaxf(EW * c1.z, 0.0f) + fmaxf(-EH * c1.w, 0.0f);
                    if (mx < -CULL_MARGIN) pass = false;
                }
                if (pass) {
                    float b1 = (tXlo - c1.x) * c2.x - (tYlo - c1.y) * c2.y;
                    float mx = b1 + fmaxf(EW * c2.x, 0.0f) + fmaxf(-EH * c2.y, 0.0f);
                    if (mx < -CULL_MARGIN) pass = false;
                }
                if (pass) {
                    float b2 = (tXlo - c0.x) * c2.z - (tYlo - c0.y) * c2.w;
                    float mx = b2 + fmaxf(EW * c2.z, 0.0f) + fmaxf(-EH * c2.w, 0.0f);
                    if (mx < -CULL_MARGIN) pass = false;
                }
            }
        }
        unsigned bal = __ballot_sync(0xffffffffu, pass);
        if (lane == 0) sWcnt[wrp] = __popc(bal);
        __syncthreads();
        int wbase = 0, M = 0;
        #pragma unroll
        for (int k = 0; k < 8; k++) {
            int c = sWcnt[k];
            wbase += (k < wrp) ? c : 0;
            M += c;
        }
        if (pass) {
            int pos = wbase + __popc(bal & ((1u << lane) - 1u));
            sF0[pos] = c0;
            sF1[pos] = c1;
            sF2[pos] = c2;
            sF3[pos] = c3;
            sF4[pos] = s_F4[triBase + f];
            sZ [pos] = s_sz[triBase + f];
            sFl[pos] = s_bf[triBase + f];
        }
        __syncthreads();

        for (int i = 0; i < M; i++) {
            // periodic block-wide break: floors are nondecreasing in sorted
            // order, so if every thread's bound beats floor[i], nothing later
            // (this chunk or any future chunk) can win or tie.
            if ((i & 31) == 0 && i != 0) {
                if (__syncthreads_and(bd_bound < sFl[i])) { finished = true; break; }
            }
            // depth skip: candidate cannot beat (or tie) either pixel's best
            if (sZ[i] > bd_bound) continue;
            float4 F0v = sF0[i], F1v = sF1[i], F2v = sF2[i], F3v = sF3[i];
            #pragma unroll
            for (int p = 0; p < 2; p++) {
                float px = p ? pxB : pxA;
                // reference edge functions (sign-flipped; inside ⟺ w >= 0)
                float w0 = edge_fn(__fsub_rn(px, F0v.z), F1v.z, __fsub_rn(py, F0v.w), F1v.w);
                float w1 = edge_fn(__fsub_rn(px, F1v.x), F2v.x, __fsub_rn(py, F1v.y), F2v.y);
                float w2 = edge_fn(__fsub_rn(px, F0v.x), F2v.z, __fsub_rn(py, F0v.y), F2v.w);
                if (fminf(w0, fminf(w1, w2)) >= 0.0f) {
                    float zia = fmaf(w0, F3v.y, fmaf(w1, F3v.z, __fmul_rn(w2, F3v.w)));
                    if (zia > fmaxf(__fmul_rn(best_zi[p], 0.999f), 2.0e-9f)) {
                        float4 F4v = sF4[i];
                        float t0 = __fdiv_rn(__fdiv_rn(w0, F3v.x), F4v.x);
                        float t1 = __fdiv_rn(__fdiv_rn(w1, F3v.x), F4v.y);
                        float t2 = __fdiv_rn(__fdiv_rn(w2, F3v.x), F4v.z);
                        float zie = __fadd_rn(__fadd_rn(t0, t1), t2);
                        if (zie > EPSF) {
                            float d = __fdiv_rn(1.0f, zie);
                            int fi = __float_as_int(F4v.w);
                            // order-independent first-min tie-break
                            if (d < best_d[p] || (d == best_d[p] && fi < best_i[p])) {
                                best_d[p] = d; best_zi[p] = zie; best_i[p] = fi;
                                bd_bound = fmaxf(best_d[0], best_d[1]) * 1.0001f;
                            }
                        }
                    }
                }
            }
        }
        if (finished) break;
        // block-level early termination: all threads beat the remaining lower bound
        float nf = (base + TCH < F) ? s_bf[triBase + base + TCH] : BIGF;
        int done = __syncthreads_and(bd_bound < nf);
        if (done) break;
    }

    // ---------------- epilogue: interp + texture + writes ----------------
    size_t HW   = (size_t)Hpix * Wpix;
    size_t m_off = (size_t)N * 3 * HW;
    size_t d_off = m_off + (size_t)N * HW;
    size_t v_off = d_off + (size_t)N * HW;
    size_t b_off = v_off + (size_t)N * HW * 2;
    size_t i_off = b_off + (size_t)N * 3 * HW;

    #pragma unroll
    for (int p = 0; p < 2; p++) {
        int wx = p ? wxB : wxA;
        float px = p ? pxB : pxA;
        size_t pix = ((size_t)n * Hpix + hy) * Wpix + wx;

        float rc0 = 0.f, rc1 = 0.f, rc2 = 0.f;
        float depth = 0.f, vtxv = 0.f, vtyv = 0.f, ba0 = 0.f, ba1 = 0.f, ba2 = 0.f;
        bool msk = best_d[p] < BIGF;
        if (msk) {
            int fidx = best_i[p];
            const float* vp = g_vpix + (size_t)n * V * 3;
            int i0 = vi[fidx*3+0]*3, i1 = vi[fidx*3+1]*3, i2 = vi[fidx*3+2]*3;
            float X0 = vp[i0], Y0 = vp[i0+1], Z0 = vp[i0+2];
            float X1 = vp[i1], Y1 = vp[i1+1], Z1 = vp[i1+2];
            float X2 = vp[i2], Y2 = vp[i2+1], Z2 = vp[i2+2];
            float w0 = edge_fn(__fsub_rn(px,X1), __fsub_rn(Y2,Y1), __fsub_rn(py,Y1), __fsub_rn(X2,X1));
            float w1 = edge_fn(__fsub_rn(px,X2), __fsub_rn(Y0,Y2), __fsub_rn(py,Y2), __fsub_rn(X0,X2));
            float w2 = edge_fn(__fsub_rn(px,X0), __fsub_rn(Y1,Y0), __fsub_rn(py,Y0), __fsub_rn(X1,X0));
            float area = edge_fn(__fsub_rn(X2,X0), __fsub_rn(Y1,Y0), __fsub_rn(Y2,Y0), __fsub_rn(X1,X0));
            float sa = (fabsf(area) > EPSF) ? area : 1.0f;
            float b0 = __fdiv_rn(w0, sa), b1 = __fdiv_rn(w1, sa), b2 = __fdiv_rn(w2, sa);
            float bz0 = __fdiv_rn(b0, fmaxf(Z0, EPSF));
            float bz1 = __fdiv_rn(b1, fmaxf(Z1, EPSF));
            float bz2 = __fdiv_rn(b2, fmaxf(Z2, EPSF));
            float zis = fmaxf(__fadd_rn(__fadd_rn(bz0, bz1), bz2), EPSF);
            ba0 = __fdiv_rn(bz0, zis); ba1 = __fdiv_rn(bz1, zis); ba2 = __fdiv_rn(bz2, zis);
            depth = __fdiv_rn(1.0f, zis);

            int t0i = vti[fidx*3+0]*2, t1i = vti[fidx*3+1]*2, t2i = vti[fidx*3+2]*2;
            float u0 = vt[t0i], tv0 = __fsub_rn(1.0f, vt[t0i+1]);
            float u1 = vt[t1i], tv1 = __fsub_rn(1.0f, vt[t1i+1]);
            float u2 = vt[t2i], tv2 = __fsub_rn(1.0f, vt[t2i+1]);
            vtxv = __fadd_rn(__fadd_rn(__fmul_rn(ba0,u0), __fmul_rn(ba1,u1)), __fmul_rn(ba2,u2));
            vtyv = __fadd_rn(__fadd_rn(__fmul_rn(ba0,tv0), __fmul_rn(ba1,tv1)), __fmul_rn(ba2,tv2));

            float gx = __fsub_rn(__fmul_rn(vtxv, 2.0f), 1.0f);
            float gy = __fsub_rn(__fmul_rn(vtyv, 2.0f), 1.0f);
            float ix = __fsub_rn(__fmul_rn(__fmul_rn(__fadd_rn(gx,1.0f), 0.5f), (float)Wt), 0.5f);
            float iy = __fsub_rn(__fmul_rn(__fmul_rn(__fadd_rn(gy,1.0f), 0.5f), (float)Ht), 0.5f);
            float xf = floorf(ix), yf = floorf(iy);
            float fx = __fsub_rn(ix, xf), fy = __fsub_rn(iy, yf);
            int x0i = min(max((int)xf,     0), Wt - 1);
            int x1i = min(max((int)xf + 1, 0), Wt - 1);
            int y0i = min(max((int)yf,     0), Ht - 1);
            int y1i = min(max((int)yf + 1, 0), Ht - 1);
            float ofx = __fsub_rn(1.0f, fx), ofy = __fsub_rn(1.0f, fy);
            const float* tc = tex + (size_t)n * 3 * Ht * Wt;
            #pragma unroll
            for (int c = 0; c < 3; c++) {
                const float* tcc = tc + (size_t)c * Ht * Wt;
                float v00 = __ldg(tcc + (size_t)y0i * Wt + x0i);
                float v01 = __ldg(tcc + (size_t)y0i * Wt + x1i);
                float v10 = __ldg(tcc + (size_t)y1i * Wt + x0i);
                float v11 = __ldg(tcc + (size_t)y1i * Wt + x1i);
                float top = __fadd_rn(__fmul_rn(v00, ofx), __fmul_rn(v01, fx));
                float bot = __fadd_rn(__fmul_rn(v10, ofx), __fmul_rn(v11, fx));
                float rv  = __fadd_rn(__fmul_rn(top, ofy), __fmul_rn(bot, fy));
                if (c == 0) rc0 = rv; else if (c == 1) rc1 = rv; else rc2 = rv;
            }
        }

        out[((size_t)(n*3+0) * Hpix + hy) * Wpix + wx] = rc0;
        out[((size_t)(n*3+1) * Hpix + hy) * Wpix + wx] = rc1;
        out[((size_t)(n*3+2) * Hpix + hy) * Wpix + wx] = rc2;
        out[m_off + pix] = msk ? 1.0f : 0.0f;
        out[d_off + pix] = depth;
        out[v_off + pix*2 + 0] = vtxv;
        out[v_off + pix*2 + 1] = vtyv;
        out[b_off + ((size_t)(n*3+0) * Hpix + hy) * Wpix + wx] = ba0;
        out[b_off + ((size_t)(n*3+1) * Hpix + hy) * Wpix + wx] = ba1;
        out[b_off + ((size_t)(n*3+2) * Hpix + hy) * Wpix + wx] = ba2;
        out[i_off + pix] = (float)best_i[p];
    }
}

// ----------------------------------------------------------------
extern "C" void kernel_launch(void* const* d_in, const int* in_sizes, int n_in,
                              void* d_out, int out_size)
{
    const float* v       = (const float*)d_in[0];
    const float* tex     = (const float*)d_in[1];
    const float* vt      = (const float*)d_in[2];
    const int*   vi      = (const int*)  d_in[3];
    const int*   vti     = (const int*)  d_in[4];
    const float* campos  = (const float*)d_in[5];
    const float* camrot  = (const float*)d_in[6];
    const float* focal   = (const float*)d_in[7];
    const float* princpt = (const float*)d_in[8];

    int N = in_sizes[5] / 3;
    int V = in_sizes[0] / (3 * N);
    int F = in_sizes[3] / 3;
    int texPer = in_sizes[1] / (3 * N);
    int Wt = (int)(sqrt((double)texPer) + 0.5);
    int Ht = texPer / Wt;

    // reset sort state via memset nodes (no init kernel launch)
    void *p_hist, *p_cur, *p_zmin, *p_zmax;
    cudaGetSymbolAddress(&p_hist, g_hist);
    cudaGetSymbolAddress(&p_cur,  g_cursor);
    cudaGetSymbolAddress(&p_zmin, g_zmin);
    cudaGetSymbolAddress(&p_zmax, g_zmax);
    cudaMemsetAsync(p_hist, 0,    (size_t)N * NB * sizeof(int));
    cudaMemsetAsync(p_cur,  0,    (size_t)N * NB * sizeof(int));
    cudaMemsetAsync(p_zmin, 0xFF, (size_t)N * sizeof(unsigned));
    cudaMemsetAsync(p_zmax, 0x00, (size_t)N * sizeof(unsigned));

    project_kernel<<<(N * V + 255) / 256, 256>>>(v, campos, camrot, focal, princpt, N, V);
    setup_kernel<<<(N * F + 255) / 256, 256>>>(vi, N, V, F);
    scatter_kernel<<<(N * F + 255) / 256, 256>>>(N, F);
    dim3 grid(Wpix / TW, Hpix / TH, N);
    raster_kernel<<<grid, dim3(16, 16)>>>(vi, vti, vt, tex, (float*)d_out, N, V, F, Ht, Wt);
}

// round 15
// speedup vs baseline: 1.1640x; 1.1640x over previous
#include <cuda_runtime.h>
#include <math.h>

#define Hpix 512
#define Wpix 512
#define EPSF 1e-8f
#define BIGF 1e30f
#define MAXN 4
#define MAXV 8192
#define MAXF 8192
#define TW 32
#define TH 16
#define TCH  256
#define NB   64
#define CULL_MARGIN 8.0f

// ---- scratch (static device globals: no allocations allowed) ----
__device__ float  g_vpix[MAXN * MAXV * 3];
// unsorted (setup output)
__device__ float4 g_B [MAXN * MAXF];
__device__ float4 g_F0[MAXN * MAXF];
__device__ float4 g_F1[MAXN * MAXF];
__device__ float4 g_F2[MAXN * MAXF];
__device__ float4 g_F3[MAXN * MAXF];
__device__ float4 g_F4[MAXN * MAXF];
__device__ float  g_minz[MAXN * MAXF];
__device__ int    g_bucket[MAXN * MAXF];
// sorted (scatter output)
__device__ float4 s_B [MAXN * MAXF];
__device__ float4 s_F0[MAXN * MAXF];
__device__ float4 s_F1[MAXN * MAXF];
__device__ float4 s_F2[MAXN * MAXF];
__device__ float4 s_F3[MAXN * MAXF];
__device__ float4 s_F4[MAXN * MAXF];
__device__ float  s_sz[MAXN * MAXF];   // min vertex z (clamped) per sorted candidate
__device__ float  s_bf[MAXN * MAXF];   // conservative bucket floor (nondecreasing)
// sort bookkeeping (reset by memset nodes each launch)
__device__ int      g_hist  [MAXN * NB];
__device__ int      g_cursor[MAXN * NB];
__device__ unsigned g_zmin[MAXN];   // monotone-encoded min vertex z (init 0xFFFFFFFF)
__device__ unsigned g_zmax[MAXN];   // monotone-encoded max vertex z (init 0)

// monotone float<->uint mapping (works for any sign)
__device__ __forceinline__ unsigned fkey(float f) {
    unsigned b = __float_as_uint(f);
    return (b & 0x80000000u) ? ~b : (b | 0x80000000u);
}
__device__ __forceinline__ float funkey(unsigned u) {
    return (u & 0x80000000u) ? __uint_as_float(u ^ 0x80000000u)
                             : __uint_as_float(~u);
}

// edge function exactly as XLA:GPU contracts it: (a*b - c*d) -> fma(a,b,-(c*d))
__device__ __forceinline__ float edge_fn(float a, float b, float c, float d) {
    return __fmaf_rn(a, b, -__fmul_rn(c, d));
}

// ----------------------------------------------------------------
// Kernel 1: project vertices -> v_pix (bitwise-exact for identity cam)
// ----------------------------------------------------------------
__global__ void project_kernel(const float* __restrict__ v,
                               const float* __restrict__ campos,
                               const float* __restrict__ camrot,
                               const float* __restrict__ focal,
                               const float* __restrict__ princpt,
                               int N, int V)
{
    int idx = blockIdx.x * blockDim.x + threadIdx.x;
    if (idx >= N * V) return;
    int n = idx / V;
    const float* vv = v + (size_t)idx * 3;
    float dx = __fsub_rn(vv[0], campos[n*3+0]);
    float dy = __fsub_rn(vv[1], campos[n*3+1]);
    float dz = __fsub_rn(vv[2], campos[n*3+2]);
    const float* R = camrot + n*9;
    float c0 = __fadd_rn(__fadd_rn(__fmul_rn(R[0],dx), __fmul_rn(R[1],dy)), __fmul_rn(R[2],dz));
    float c1 = __fadd_rn(__fadd_rn(__fmul_rn(R[3],dx), __fmul_rn(R[4],dy)), __fmul_rn(R[5],dz));
    float c2 = __fadd_rn(__fadd_rn(__fmul_rn(R[6],dx), __fmul_rn(R[7],dy)), __fmul_rn(R[8],dz));
    float z  = fmaxf(c2, EPSF);
    float u  = __fdiv_rn(c0, z);
    float w  = __fdiv_rn(c1, z);
    const float* Fm = focal + n*4;
    float X = __fadd_rn(__fadd_rn(__fmul_rn(Fm[0],u), __fmul_rn(Fm[1],w)), princpt[n*2+0]);
    float Y = __fadd_rn(__fadd_rn(__fmul_rn(Fm[2],u), __fmul_rn(Fm[3],w)), princpt[n*2+1]);
    g_vpix[(size_t)idx*3+0] = X;
    g_vpix[(size_t)idx*3+1] = Y;
    g_vpix[(size_t)idx*3+2] = c2;
    float zc = fmaxf(c2, EPSF);
    atomicMin(&g_zmin[n], fkey(zc));
    atomicMax(&g_zmax[n], fkey(zc));
}

// ----------------------------------------------------------------
// Kernel 2: per-(view, triangle) setup with sign-flipped edges
// ----------------------------------------------------------------
__global__ void setup_kernel(const int* __restrict__ vi, int N, int V, int F)
{
    int idx = blockIdx.x * blockDim.x + threadIdx.x;
    if (idx >= N * F) return;
    int n = idx / F, f = idx - n * F;
    const float* vp = g_vpix + (size_t)n * V * 3;
    int i0 = vi[f*3+0]*3, i1 = vi[f*3+1]*3, i2 = vi[f*3+2]*3;
    float x0 = vp[i0], y0 = vp[i0+1], z0 = vp[i0+2];
    float x1 = vp[i1], y1 = vp[i1+1], z1 = vp[i1+2];
    float x2 = vp[i2], y2 = vp[i2+1], z2 = vp[i2+2];

    float dy21 = __fsub_rn(y2,y1), dx21 = __fsub_rn(x2,x1);
    float dy02 = __fsub_rn(y0,y2), dx02 = __fsub_rn(x0,x2);
    float dy10 = __fsub_rn(y1,y0), dx10 = __fsub_rn(x1,x0);
    float area = edge_fn(__fsub_rn(x2,x0), dy10, __fsub_rn(y2,y0), dx10);
    float z0m = fmaxf(z0, EPSF), z1m = fmaxf(z1, EPSF), z2m = fmaxf(z2, EPSF);
    bool valid = (fabsf(area) > EPSF) && (z0 > EPSF) && (z1 > EPSF) && (z2 > EPSF);

    float s = (area > 0.0f) ? 1.0f : -1.0f;   // exact sign flip
    float areaf = s*area;                     // |area|

    float R0 = __frcp_rn(__fmul_rn(areaf, z0m));
    float R1 = __frcp_rn(__fmul_rn(areaf, z1m));
    float R2 = __frcp_rn(__fmul_rn(areaf, z2m));

    float xmn, xmx, ymn, ymx;
    if (valid) {
        xmn = fminf(fminf(x0,x1),x2) - 1.0f;
        xmx = fmaxf(fmaxf(x0,x1),x2) + 1.0f;
        ymn = fminf(fminf(y0,y1),y2) - 1.0f;
        ymx = fmaxf(fmaxf(y0,y1),y2) + 1.0f;
    } else {
        xmn = BIGF; xmx = -BIGF; ymn = BIGF; ymx = -BIGF;
    }
    g_B [idx] = make_float4(xmn, xmx, ymn, ymx);
    g_F0[idx] = make_float4(x0, y0, x1, y1);
    g_F1[idx] = make_float4(x2, y2, s*dy21, s*dx21);
    g_F2[idx] = make_float4(s*dy02, s*dx02, s*dy10, s*dx10);
    g_F3[idx] = make_float4(areaf, R0, R1, R2);
    g_F4[idx] = make_float4(z0m, z1m, z2m, __int_as_float(f));

    // bucket by min vertex z
    float minz = fminf(fminf(z0m, z1m), z2m);
    float zlo = funkey(g_zmin[n]);
    float zhi = funkey(g_zmax[n]);
    float range = zhi - zlo;
    int b;
    if (range > 1e-6f) {
        b = (int)((minz - zlo) * ((float)NB / range));
        b = min(max(b, 0), NB - 1);
    } else b = 0;
    g_minz[idx] = minz;
    g_bucket[idx] = b;
    atomicAdd(&g_hist[n*NB + b], 1);
}

// ----------------------------------------------------------------
// Kernel 3: scatter triangles into bucket-sorted order (full payload).
// Exclusive bucket prefix computed inline (<=63 L2-hot loads).
// ----------------------------------------------------------------
__global__ void scatter_kernel(int N, int F)
{
    int idx = blockIdx.x * blockDim.x + threadIdx.x;
    if (idx >= N * F) return;
    int n = idx / F;
    int b = g_bucket[idx];
    int off = 0;
    for (int k = 0; k < b; k++) off += g_hist[n*NB + k];
    int slot = off + atomicAdd(&g_cursor[n*NB + b], 1);
    int dst = n * F + slot;
    s_B [dst] = g_B [idx];
    s_F0[dst] = g_F0[idx];
    s_F1[dst] = g_F1[idx];
    s_F2[dst] = g_F2[idx];
    s_F3[dst] = g_F3[idx];
    s_F4[dst] = g_F4[idx];
    s_sz[dst] = g_minz[idx];
    float zlo = funkey(g_zmin[n]);
    float zhi = funkey(g_zmax[n]);
    // conservative under-estimate of the bucket's lower z bound
    float bf = __fmaf_rn((float)b, (zhi - zlo) * (1.0f / NB), zlo);
    s_bf[dst] = bf * 0.9999f - 1e-6f;
}

// packed per-candidate record for the raster inner loop (AoS: one base
// address + constant offsets instead of 5 independent smem streams)
struct Tri {
    float4 F0, F1, F2, F3, F4;
};

// ----------------------------------------------------------------
// Kernel 4: 32x16 tiles, 2 pixels/thread, edge-cull compaction,
// sorted candidates + z-skip + chunk-level block early break.
// ----------------------------------------------------------------
__global__ void __launch_bounds__(256)
raster_kernel(const int* __restrict__ vi, const int* __restrict__ vti,
              const float* __restrict__ vt, const float* __restrict__ tex,
              float* __restrict__ out, int N, int V, int F, int Ht, int Wt)
{
    __shared__ Tri   sTri[TCH];
    __shared__ float sZ[TCH];
    __shared__ int sWcnt[8];

    int n = blockIdx.z;
    int tx0 = blockIdx.x * TW, ty0 = blockIdx.y * TH;
    int wxA = tx0 + threadIdx.x;
    int wxB = wxA + 16;
    int hy  = ty0 + threadIdx.y;
    float pxA = (float)wxA, pxB = (float)wxB, py = (float)hy;
    float tXlo = (float)tx0, tXhi = (float)(tx0 + TW - 1);
    float tYlo = (float)ty0, tYhi = (float)(ty0 + TH - 1);
    int t = threadIdx.y * 16 + threadIdx.x;
    int lane = t & 31, wrp = t >> 5;
    size_t triBase = (size_t)n * F;

    float best_d[2]  = {BIGF, BIGF};
    float best_zi[2] = {0.0f, 0.0f};
    int   best_i[2]  = {-1, -1};
    float bd_bound = BIGF;   // max(best_d)*(1+1e-4), candidate skip threshold

    const float EW = (float)(TW - 1), EH = (float)(TH - 1);

    for (int base = 0; base < F; base += TCH) {
        int f = base + t;
        bool pass = false;
        float4 c0, c1, c2, c3;
        if (f < F) {
            float4 bb = s_B[triBase + f];
            pass = (bb.y >= tXlo) && (bb.x <= tXhi) && (bb.w >= tYlo) && (bb.z <= tYhi);
            if (pass) {
                c0 = s_F0[triBase + f];
                c1 = s_F1[triBase + f];
                c2 = s_F2[triBase + f];
                c3 = s_F3[triBase + f];
                {
                    float b0 = (tXlo - c0.z) * c1.z - (tYlo - c0.w) * c1.w;
                    float mx = b0 + fmaxf(EW * c1.z, 0.0f) + fmaxf(-EH * c1.w, 0.0f);
                    if (mx < -CULL_MARGIN) pass = false;
                }
                if (pass) {
                    float b1 = (tXlo - c1.x) * c2.x - (tYlo - c1.y) * c2.y;
                    float mx = b1 + fmaxf(EW * c2.x, 0.0f) + fmaxf(-EH * c2.y, 0.0f);
                    if (mx < -CULL_MARGIN) pass = false;
                }
                if (pass) {
                    float b2 = (tXlo - c0.x) * c2.z - (tYlo - c0.y) * c2.w;
                    float mx = b2 + fmaxf(EW * c2.z, 0.0f) + fmaxf(-EH * c2.w, 0.0f);
                    if (mx < -CULL_MARGIN) pass = false;
                }
            }
        }
        unsigned bal = __ballot_sync(0xffffffffu, pass);
        if (lane == 0) sWcnt[wrp] = __popc(bal);
        __syncthreads();
        int wbase = 0, M = 0;
        #pragma unroll
        for (int k = 0; k < 8; k++) {
            int c = sWcnt[k];
            wbase += (k < wrp) ? c : 0;
            M += c;
        }
        if (pass) {
            int pos = wbase + __popc(bal & ((1u << lane) - 1u));
            sTri[pos].F0 = c0;
            sTri[pos].F1 = c1;
            sTri[pos].F2 = c2;
            sTri[pos].F3 = c3;
            sTri[pos].F4 = s_F4[triBase + f];
            sZ  [pos]    = s_sz[triBase + f];
        }
        __syncthreads();

        for (int i = 0; i < M; i++) {
            // depth skip: candidate cannot beat (or tie) either pixel's best
            if (sZ[i] > bd_bound) continue;
            float4 F0v = sTri[i].F0, F1v = sTri[i].F1,
                   F2v = sTri[i].F2, F3v = sTri[i].F3;
            #pragma unroll
            for (int p = 0; p < 2; p++) {
                float px = p ? pxB : pxA;
                // reference edge functions (sign-flipped; inside ⟺ w >= 0)
                float w0 = edge_fn(__fsub_rn(px, F0v.z), F1v.z, __fsub_rn(py, F0v.w), F1v.w);
                float w1 = edge_fn(__fsub_rn(px, F1v.x), F2v.x, __fsub_rn(py, F1v.y), F2v.y);
                float w2 = edge_fn(__fsub_rn(px, F0v.x), F2v.z, __fsub_rn(py, F0v.y), F2v.w);
                if (fminf(w0, fminf(w1, w2)) >= 0.0f) {
                    float zia = fmaf(w0, F3v.y, fmaf(w1, F3v.z, __fmul_rn(w2, F3v.w)));
                    if (zia > fmaxf(__fmul_rn(best_zi[p], 0.999f), 2.0e-9f)) {
                        float4 F4v = sTri[i].F4;
                        float t0 = __fdiv_rn(__fdiv_rn(w0, F3v.x), F4v.x);
                        float t1 = __fdiv_rn(__fdiv_rn(w1, F3v.x), F4v.y);
                        float t2 = __fdiv_rn(__fdiv_rn(w2, F3v.x), F4v.z);
                        float zie = __fadd_rn(__fadd_rn(t0, t1), t2);
                        if (zie > EPSF) {
                            float d = __fdiv_rn(1.0f, zie);
                            int fi = __float_as_int(F4v.w);
                            // order-independent first-min tie-break
                            if (d < best_d[p] || (d == best_d[p] && fi < best_i[p])) {
                                best_d[p] = d; best_zi[p] = zie; best_i[p] = fi;
                                bd_bound = fmaxf(best_d[0], best_d[1]) * 1.0001f;
                            }
                        }
                    }
                }
            }
        }
        // block-level early termination: all threads beat the remaining lower bound
        float nf = (base + TCH < F) ? s_bf[triBase + base + TCH] : BIGF;
        int done = __syncthreads_and(bd_bound < nf);
        if (done) break;
    }

    // ---------------- epilogue: interp + texture + writes ----------------
    size_t HW   = (size_t)Hpix * Wpix;
    size_t m_off = (size_t)N * 3 * HW;
    size_t d_off = m_off + (size_t)N * HW;
    size_t v_off = d_off + (size_t)N * HW;
    size_t b_off = v_off + (size_t)N * HW * 2;
    size_t i_off = b_off + (size_t)N * 3 * HW;

    #pragma unroll
    for (int p = 0; p < 2; p++) {
        int wx = p ? wxB : wxA;
        float px = p ? pxB : pxA;
        size_t pix = ((size_t)n * Hpix + hy) * Wpix + wx;

        float rc0 = 0.f, rc1 = 0.f, rc2 = 0.f;
        float depth = 0.f, vtxv = 0.f, vtyv = 0.f, ba0 = 0.f, ba1 = 0.f, ba2 = 0.f;
        bool msk = best_d[p] < BIGF;
        if (msk) {
            int fidx = best_i[p];
            const float* vp = g_vpix + (size_t)n * V * 3;
            int i0 = vi[fidx*3+0]*3, i1 = vi[fidx*3+1]*3, i2 = vi[fidx*3+2]*3;
            float X0 = vp[i0], Y0 = vp[i0+1], Z0 = vp[i0+2];
            float X1 = vp[i1], Y1 = vp[i1+1], Z1 = vp[i1+2];
            float X2 = vp[i2], Y2 = vp[i2+1], Z2 = vp[i2+2];
            float w0 = edge_fn(__fsub_rn(px,X1), __fsub_rn(Y2,Y1), __fsub_rn(py,Y1), __fsub_rn(X2,X1));
            float w1 = edge_fn(__fsub_rn(px,X2), __fsub_rn(Y0,Y2), __fsub_rn(py,Y2), __fsub_rn(X0,X2));
            float w2 = edge_fn(__fsub_rn(px,X0), __fsub_rn(Y1,Y0), __fsub_rn(py,Y0), __fsub_rn(X1,X0));
            float area = edge_fn(__fsub_rn(X2,X0), __fsub_rn(Y1,Y0), __fsub_rn(Y2,Y0), __fsub_rn(X1,X0));
            float sa = (fabsf(area) > EPSF) ? area : 1.0f;
            float b0 = __fdiv_rn(w0, sa), b1 = __fdiv_rn(w1, sa), b2 = __fdiv_rn(w2, sa);
            float bz0 = __fdiv_rn(b0, fmaxf(Z0, EPSF));
            float bz1 = __fdiv_rn(b1, fmaxf(Z1, EPSF));
            float bz2 = __fdiv_rn(b2, fmaxf(Z2, EPSF));
            float zis = fmaxf(__fadd_rn(__fadd_rn(bz0, bz1), bz2), EPSF);
            ba0 = __fdiv_rn(bz0, zis); ba1 = __fdiv_rn(bz1, zis); ba2 = __fdiv_rn(bz2, zis);
            depth = __fdiv_rn(1.0f, zis);

            int t0i = vti[fidx*3+0]*2, t1i = vti[fidx*3+1]*2, t2i = vti[fidx*3+2]*2;
            float u0 = vt[t0i], tv0 = __fsub_rn(1.0f, vt[t0i+1]);
            float u1 = vt[t1i], tv1 = __fsub_rn(1.0f, vt[t1i+1]);
            float u2 = vt[t2i], tv2 = __fsub_rn(1.0f, vt[t2i+1]);
            vtxv = __fadd_rn(__fadd_rn(__fmul_rn(ba0,u0), __fmul_rn(ba1,u1)), __fmul_rn(ba2,u2));
            vtyv = __fadd_rn(__fadd_rn(__fmul_rn(ba0,tv0), __fmul_rn(ba1,tv1)), __fmul_rn(ba2,tv2));

            float gx = __fsub_rn(__fmul_rn(vtxv, 2.0f), 1.0f);
            float gy = __fsub_rn(__fmul_rn(vtyv, 2.0f), 1.0f);
            float ix = __fsub_rn(__fmul_rn(__fmul_rn(__fadd_rn(gx,1.0f), 0.5f), (float)Wt), 0.5f);
            float iy = __fsub_rn(__fmul_rn(__fmul_rn(__fadd_rn(gy,1.0f), 0.5f), (float)Ht), 0.5f);
            float xf = floorf(ix), yf = floorf(iy);
            float fx = __fsub_rn(ix, xf), fy = __fsub_rn(iy, yf);
            int x0i = min(max((int)xf,     0), Wt - 1);
            int x1i = min(max((int)xf + 1, 0), Wt - 1);
            int y0i = min(max((int)yf,     0), Ht - 1);
            int y1i = min(max((int)yf + 1, 0), Ht - 1);
            float ofx = __fsub_rn(1.0f, fx), ofy = __fsub_rn(1.0f, fy);
            const float* tc = tex + (size_t)n * 3 * Ht * Wt;
            #pragma unroll
            for (int c = 0; c < 3; c++) {
                const float* tcc = tc + (size_t)c * Ht * Wt;
                float v00 = __ldg(tcc + (size_t)y0i * Wt + x0i);
                float v01 = __ldg(tcc + (size_t)y0i * Wt + x1i);
                float v10 = __ldg(tcc + (size_t)y1i * Wt + x0i);
                float v11 = __ldg(tcc + (size_t)y1i * Wt + x1i);
                float top = __fadd_rn(__fmul_rn(v00, ofx), __fmul_rn(v01, fx));
                float bot = __fadd_rn(__fmul_rn(v10, ofx), __fmul_rn(v11, fx));
                float rv  = __fadd_rn(__fmul_rn(top, ofy), __fmul_rn(bot, fy));
                if (c == 0) rc0 = rv; else if (c == 1) rc1 = rv; else rc2 = rv;
            }
        }

        out[((size_t)(n*3+0) * Hpix + hy) * Wpix + wx] = rc0;
        out[((size_t)(n*3+1) * Hpix + hy) * Wpix + wx] = rc1;
        out[((size_t)(n*3+2) * Hpix + hy) * Wpix + wx] = rc2;
        out[m_off + pix] = msk ? 1.0f : 0.0f;
        out[d_off + pix] = depth;
        out[v_off + pix*2 + 0] = vtxv;
        out[v_off + pix*2 + 1] = vtyv;
        out[b_off + ((size_t)(n*3+0) * Hpix + hy) * Wpix + wx] = ba0;
        out[b_off + ((size_t)(n*3+1) * Hpix + hy) * Wpix + wx] = ba1;
        out[b_off + ((size_t)(n*3+2) * Hpix + hy) * Wpix + wx] = ba2;
        out[i_off + pix] = (float)best_i[p];
    }
}

// ----------------------------------------------------------------
extern "C" void kernel_launch(void* const* d_in, const int* in_sizes, int n_in,
                              void* d_out, int out_size)
{
    const float* v       = (const float*)d_in[0];
    const float* tex     = (const float*)d_in[1];
    const float* vt      = (const float*)d_in[2];
    const int*   vi      = (const int*)  d_in[3];
    const int*   vti     = (const int*)  d_in[4];
    const float* campos  = (const float*)d_in[5];
    const float* camrot  = (const float*)d_in[6];
    const float* focal   = (const float*)d_in[7];
    const float* princpt = (const float*)d_in[8];

    int N = in_sizes[5] / 3;
    int V = in_sizes[0] / (3 * N);
    int F = in_sizes[3] / 3;
    int texPer = in_sizes[1] / (3 * N);
    int Wt = (int)(sqrt((double)texPer) + 0.5);
    int Ht = texPer / Wt;

    // reset sort state via memset nodes (no init kernel launch)
    void *p_hist, *p_cur, *p_zmin, *p_zmax;
    cudaGetSymbolAddress(&p_hist, g_hist);
    cudaGetSymbolAddress(&p_cur,  g_cursor);
    cudaGetSymbolAddress(&p_zmin, g_zmin);
    cudaGetSymbolAddress(&p_zmax, g_zmax);
    cudaMemsetAsync(p_hist, 0,    (size_t)N * NB * sizeof(int));
    cudaMemsetAsync(p_cur,  0,    (size_t)N * NB * sizeof(int));
    cudaMemsetAsync(p_zmin, 0xFF, (size_t)N * sizeof(unsigned));
    cudaMemsetAsync(p_zmax, 0x00, (size_t)N * sizeof(unsigned));

    project_kernel<<<(N * V + 255) / 256, 256>>>(v, campos, camrot, focal, princpt, N, V);
    setup_kernel<<<(N * F + 255) / 256, 256>>>(vi, N, V, F);
    scatter_kernel<<<(N * F + 255) / 256, 256>>>(N, F);
    dim3 grid(Wpix / TW, Hpix / TH, N);
    raster_kernel<<<grid, dim3(16, 16)>>>(vi, vti, vt, tex, (float*)d_out, N, V, F, Ht, Wt);
}

// round 17
// speedup vs baseline: 1.2035x; 1.0339x over previous
#include <cuda_runtime.h>
#include <math.h>

#define Hpix 512
#define Wpix 512
#define EPSF 1e-8f
#define BIGF 1e30f
#define MAXN 4
#define MAXV 8192
#define MAXF 8192
#define TW 32
#define TH 16
#define TCH  256
#define NB   64
#define CULL_MARGIN 8.0f

// ---- scratch (static device globals: no allocations allowed) ----
__device__ float  g_vpix[MAXN * MAXV * 3];
// unsorted (setup output)
__device__ float4 g_B [MAXN * MAXF];
__device__ float4 g_F0[MAXN * MAXF];
__device__ float4 g_F1[MAXN * MAXF];
__device__ float4 g_F2[MAXN * MAXF];
__device__ float4 g_F3[MAXN * MAXF];
__device__ float4 g_F4[MAXN * MAXF];
__device__ float  g_minz[MAXN * MAXF];
__device__ int    g_bucket[MAXN * MAXF];
// sorted (scatter output)
__device__ float4 s_B [MAXN * MAXF];
__device__ float4 s_F0[MAXN * MAXF];
__device__ float4 s_F1[MAXN * MAXF];
__device__ float4 s_F2[MAXN * MAXF];
__device__ float4 s_F3[MAXN * MAXF];
__device__ float4 s_F4[MAXN * MAXF];
__device__ float  s_sz[MAXN * MAXF];   // min vertex z (clamped) per sorted candidate
__device__ float  s_bf[MAXN * MAXF];   // conservative bucket floor (nondecreasing)
// sort bookkeeping (reset by memset nodes each launch)
__device__ int      g_hist  [MAXN * NB];
__device__ int      g_cursor[MAXN * NB];
__device__ unsigned g_zmin[MAXN];   // monotone-encoded min vertex z (init 0xFFFFFFFF)
__device__ unsigned g_zmax[MAXN];   // monotone-encoded max vertex z (init 0)

// monotone float<->uint mapping (works for any sign)
__device__ __forceinline__ unsigned fkey(float f) {
    unsigned b = __float_as_uint(f);
    return (b & 0x80000000u) ? ~b : (b | 0x80000000u);
}
__device__ __forceinline__ float funkey(unsigned u) {
    return (u & 0x80000000u) ? __uint_as_float(u ^ 0x80000000u)
                             : __uint_as_float(~u);
}

// edge function exactly as XLA:GPU contracts it: (a*b - c*d) -> fma(a,b,-(c*d))
__device__ __forceinline__ float edge_fn(float a, float b, float c, float d) {
    return __fmaf_rn(a, b, -__fmul_rn(c, d));
}

// ----------------------------------------------------------------
// Kernel 1: project vertices -> v_pix (bitwise-exact for identity cam)
// ----------------------------------------------------------------
__global__ void project_kernel(const float* __restrict__ v,
                               const float* __restrict__ campos,
                               const float* __restrict__ camrot,
                               const float* __restrict__ focal,
                               const float* __restrict__ princpt,
                               int N, int V)
{
    int idx = blockIdx.x * blockDim.x + threadIdx.x;
    if (idx >= N * V) return;
    int n = idx / V;
    const float* vv = v + (size_t)idx * 3;
    float dx = __fsub_rn(vv[0], campos[n*3+0]);
    float dy = __fsub_rn(vv[1], campos[n*3+1]);
    float dz = __fsub_rn(vv[2], campos[n*3+2]);
    const float* R = camrot + n*9;
    float c0 = __fadd_rn(__fadd_rn(__fmul_rn(R[0],dx), __fmul_rn(R[1],dy)), __fmul_rn(R[2],dz));
    float c1 = __fadd_rn(__fadd_rn(__fmul_rn(R[3],dx), __fmul_rn(R[4],dy)), __fmul_rn(R[5],dz));
    float c2 = __fadd_rn(__fadd_rn(__fmul_rn(R[6],dx), __fmul_rn(R[7],dy)), __fmul_rn(R[8],dz));
    float z  = fmaxf(c2, EPSF);
    float u  = __fdiv_rn(c0, z);
    float w  = __fdiv_rn(c1, z);
    const float* Fm = focal + n*4;
    float X = __fadd_rn(__fadd_rn(__fmul_rn(Fm[0],u), __fmul_rn(Fm[1],w)), princpt[n*2+0]);
    float Y = __fadd_rn(__fadd_rn(__fmul_rn(Fm[2],u), __fmul_rn(Fm[3],w)), princpt[n*2+1]);
    g_vpix[(size_t)idx*3+0] = X;
    g_vpix[(size_t)idx*3+1] = Y;
    g_vpix[(size_t)idx*3+2] = c2;
    float zc = fmaxf(c2, EPSF);
    atomicMin(&g_zmin[n], fkey(zc));
    atomicMax(&g_zmax[n], fkey(zc));
}

// ----------------------------------------------------------------
// Kernel 2: per-(view, triangle) setup with sign-flipped edges
// ----------------------------------------------------------------
__global__ void setup_kernel(const int* __restrict__ vi, int N, int V, int F)
{
    int idx = blockIdx.x * blockDim.x + threadIdx.x;
    if (idx >= N * F) return;
    int n = idx / F, f = idx - n * F;
    const float* vp = g_vpix + (size_t)n * V * 3;
    int i0 = vi[f*3+0]*3, i1 = vi[f*3+1]*3, i2 = vi[f*3+2]*3;
    float x0 = vp[i0], y0 = vp[i0+1], z0 = vp[i0+2];
    float x1 = vp[i1], y1 = vp[i1+1], z1 = vp[i1+2];
    float x2 = vp[i2], y2 = vp[i2+1], z2 = vp[i2+2];

    float dy21 = __fsub_rn(y2,y1), dx21 = __fsub_rn(x2,x1);
    float dy02 = __fsub_rn(y0,y2), dx02 = __fsub_rn(x0,x2);
    float dy10 = __fsub_rn(y1,y0), dx10 = __fsub_rn(x1,x0);
    float area = edge_fn(__fsub_rn(x2,x0), dy10, __fsub_rn(y2,y0), dx10);
    float z0m = fmaxf(z0, EPSF), z1m = fmaxf(z1, EPSF), z2m = fmaxf(z2, EPSF);
    bool valid = (fabsf(area) > EPSF) && (z0 > EPSF) && (z1 > EPSF) && (z2 > EPSF);

    float s = (area > 0.0f) ? 1.0f : -1.0f;   // exact sign flip
    float areaf = s*area;                     // |area|

    float R0 = __frcp_rn(__fmul_rn(areaf, z0m));
    float R1 = __frcp_rn(__fmul_rn(areaf, z1m));
    float R2 = __frcp_rn(__fmul_rn(areaf, z2m));

    float xmn, xmx, ymn, ymx;
    if (valid) {
        xmn = fminf(fminf(x0,x1),x2) - 1.0f;
        xmx = fmaxf(fmaxf(x0,x1),x2) + 1.0f;
        ymn = fminf(fminf(y0,y1),y2) - 1.0f;
        ymx = fmaxf(fmaxf(y0,y1),y2) + 1.0f;
    } else {
        xmn = BIGF; xmx = -BIGF; ymn = BIGF; ymx = -BIGF;
    }
    g_B [idx] = make_float4(xmn, xmx, ymn, ymx);
    g_F0[idx] = make_float4(x0, y0, x1, y1);
    g_F1[idx] = make_float4(x2, y2, s*dy21, s*dx21);
    g_F2[idx] = make_float4(s*dy02, s*dx02, s*dy10, s*dx10);
    g_F3[idx] = make_float4(areaf, R0, R1, R2);
    g_F4[idx] = make_float4(z0m, z1m, z2m, __int_as_float(f));

    // bucket by min vertex z
    float minz = fminf(fminf(z0m, z1m), z2m);
    float zlo = funkey(g_zmin[n]);
    float zhi = funkey(g_zmax[n]);
    float range = zhi - zlo;
    int b;
    if (range > 1e-6f) {
        b = (int)((minz - zlo) * ((float)NB / range));
        b = min(max(b, 0), NB - 1);
    } else b = 0;
    g_minz[idx] = minz;
    g_bucket[idx] = b;
    atomicAdd(&g_hist[n*NB + b], 1);
}

// ----------------------------------------------------------------
// Kernel 3: scatter triangles into bucket-sorted order (full payload).
// Exclusive bucket prefix computed inline (<=63 L2-hot loads).
// ----------------------------------------------------------------
__global__ void scatter_kernel(int N, int F)
{
    int idx = blockIdx.x * blockDim.x + threadIdx.x;
    if (idx >= N * F) return;
    int n = idx / F;
    int b = g_bucket[idx];
    int off = 0;
    for (int k = 0; k < b; k++) off += g_hist[n*NB + k];
    int slot = off + atomicAdd(&g_cursor[n*NB + b], 1);
    int dst = n * F + slot;
    s_B [dst] = g_B [idx];
    s_F0[dst] = g_F0[idx];
    s_F1[dst] = g_F1[idx];
    s_F2[dst] = g_F2[idx];
    s_F3[dst] = g_F3[idx];
    s_F4[dst] = g_F4[idx];
    s_sz[dst] = g_minz[idx];
    float zlo = funkey(g_zmin[n]);
    float zhi = funkey(g_zmax[n]);
    // conservative under-estimate of the bucket's lower z bound
    float bf = __fmaf_rn((float)b, (zhi - zlo) * (1.0f / NB), zlo);
    s_bf[dst] = bf * 0.9999f - 1e-6f;
}

// packed per-candidate record for the raster inner loop (AoS: one base
// address + constant offsets instead of 5 independent smem streams)
struct Tri {
    float4 F0, F1, F2, F3, F4;
};

// ----------------------------------------------------------------
// Kernel 4: 32x16 tiles, 2 pixels/thread, edge-cull compaction,
// sorted candidates + z-skip + chunk-level block early break.
// __launch_bounds__(256, 4): cap at 64 regs for 4 blocks/SM occupancy.
// ----------------------------------------------------------------
__global__ void __launch_bounds__(256, 4)
raster_kernel(const int* __restrict__ vi, const int* __restrict__ vti,
              const float* __restrict__ vt, const float* __restrict__ tex,
              float* __restrict__ out, int N, int V, int F, int Ht, int Wt)
{
    __shared__ Tri   sTri[TCH];
    __shared__ float sZ[TCH];
    __shared__ int sWcnt[8];

    int n = blockIdx.z;
    int tx0 = blockIdx.x * TW, ty0 = blockIdx.y * TH;
    int wxA = tx0 + threadIdx.x;
    int wxB = wxA + 16;
    int hy  = ty0 + threadIdx.y;
    float pxA = (float)wxA, pxB = (float)wxB, py = (float)hy;
    float tXlo = (float)tx0, tXhi = (float)(tx0 + TW - 1);
    float tYlo = (float)ty0, tYhi = (float)(ty0 + TH - 1);
    int t = threadIdx.y * 16 + threadIdx.x;
    int lane = t & 31, wrp = t >> 5;
    size_t triBase = (size_t)n * F;

    float best_d[2]  = {BIGF, BIGF};
    float best_zi[2] = {0.0f, 0.0f};
    int   best_i[2]  = {-1, -1};
    float bd_bound = BIGF;   // max(best_d)*(1+1e-4), candidate skip threshold

    const float EW = (float)(TW - 1), EH = (float)(TH - 1);

    for (int base = 0; base < F; base += TCH) {
        int f = base + t;
        bool pass = false;
        float4 c0, c1, c2, c3;
        if (f < F) {
            float4 bb = s_B[triBase + f];
            pass = (bb.y >= tXlo) && (bb.x <= tXhi) && (bb.w >= tYlo) && (bb.z <= tYhi);
            if (pass) {
                c0 = s_F0[triBase + f];
                c1 = s_F1[triBase + f];
                c2 = s_F2[triBase + f];
                c3 = s_F3[triBase + f];
                {
                    float b0 = (tXlo - c0.z) * c1.z - (tYlo - c0.w) * c1.w;
                    float mx = b0 + fmaxf(EW * c1.z, 0.0f) + fmaxf(-EH * c1.w, 0.0f);
                    if (mx < -CULL_MARGIN) pass = false;
                }
                if (pass) {
                    float b1 = (tXlo - c1.x) * c2.x - (tYlo - c1.y) * c2.y;
                    float mx = b1 + fmaxf(EW * c2.x, 0.0f) + fmaxf(-EH * c2.y, 0.0f);
                    if (mx < -CULL_MARGIN) pass = false;
                }
                if (pass) {
                    float b2 = (tXlo - c0.x) * c2.z - (tYlo - c0.y) * c2.w;
                    float mx = b2 + fmaxf(EW * c2.z, 0.0f) + fmaxf(-EH * c2.w, 0.0f);
                    if (mx < -CULL_MARGIN) pass = false;
                }
            }
        }
        unsigned bal = __ballot_sync(0xffffffffu, pass);
        if (lane == 0) sWcnt[wrp] = __popc(bal);
        __syncthreads();
        int wbase = 0, M = 0;
        #pragma unroll
        for (int k = 0; k < 8; k++) {
            int c = sWcnt[k];
            wbase += (k < wrp) ? c : 0;
            M += c;
        }
        if (pass) {
            int pos = wbase + __popc(bal & ((1u << lane) - 1u));
            sTri[pos].F0 = c0;
            sTri[pos].F1 = c1;
            sTri[pos].F2 = c2;
            sTri[pos].F3 = c3;
            sTri[pos].F4 = s_F4[triBase + f];
            sZ  [pos]    = s_sz[triBase + f];
        }
        __syncthreads();

        for (int i = 0; i < M; i++) {
            // depth skip: candidate cannot beat (or tie) either pixel's best
            if (sZ[i] > bd_bound) continue;
            float4 F0v = sTri[i].F0, F1v = sTri[i].F1,
                   F2v = sTri[i].F2, F3v = sTri[i].F3;
            #pragma unroll
            for (int p = 0; p < 2; p++) {
                float px = p ? pxB : pxA;
                // reference edge functions (sign-flipped; inside ⟺ w >= 0)
                float w0 = edge_fn(__fsub_rn(px, F0v.z), F1v.z, __fsub_rn(py, F0v.w), F1v.w);
                float w1 = edge_fn(__fsub_rn(px, F1v.x), F2v.x, __fsub_rn(py, F1v.y), F2v.y);
                float w2 = edge_fn(__fsub_rn(px, F0v.x), F2v.z, __fsub_rn(py, F0v.y), F2v.w);
                if (fminf(w0, fminf(w1, w2)) >= 0.0f) {
                    float zia = fmaf(w0, F3v.y, fmaf(w1, F3v.z, __fmul_rn(w2, F3v.w)));
                    if (zia > fmaxf(__fmul_rn(best_zi[p], 0.999f), 2.0e-9f)) {
                        float4 F4v = sTri[i].F4;
                        float t0 = __fdiv_rn(__fdiv_rn(w0, F3v.x), F4v.x);
                        float t1 = __fdiv_rn(__fdiv_rn(w1, F3v.x), F4v.y);
                        float t2 = __fdiv_rn(__fdiv_rn(w2, F3v.x), F4v.z);
                        float zie = __fadd_rn(__fadd_rn(t0, t1), t2);
                        if (zie > EPSF) {
                            float d = __fdiv_rn(1.0f, zie);
                            int fi = __float_as_int(F4v.w);
                            // order-independent first-min tie-break
                            if (d < best_d[p] || (d == best_d[p] && fi < best_i[p])) {
                                best_d[p] = d; best_zi[p] = zie; best_i[p] = fi;
                                bd_bound = fmaxf(best_d[0], best_d[1]) * 1.0001f;
                            }
                        }
                    }
                }
            }
        }
        // block-level early termination: all threads beat the remaining lower bound
        float nf = (base + TCH < F) ? s_bf[triBase + base + TCH] : BIGF;
        int done = __syncthreads_and(bd_bound < nf);
        if (done) break;
    }

    // ---------------- epilogue: interp + texture + writes ----------------
    size_t HW   = (size_t)Hpix * Wpix;
    size_t m_off = (size_t)N * 3 * HW;
    size_t d_off = m_off + (size_t)N * HW;
    size_t v_off = d_off + (size_t)N * HW;
    size_t b_off = v_off + (size_t)N * HW * 2;
    size_t i_off = b_off + (size_t)N * 3 * HW;

    #pragma unroll
    for (int p = 0; p < 2; p++) {
        int wx = p ? wxB : wxA;
        float px = p ? pxB : pxA;
        size_t pix = ((size_t)n * Hpix + hy) * Wpix + wx;

        float rc0 = 0.f, rc1 = 0.f, rc2 = 0.f;
        float depth = 0.f, vtxv = 0.f, vtyv = 0.f, ba0 = 0.f, ba1 = 0.f, ba2 = 0.f;
        bool msk = best_d[p] < BIGF;
        if (msk) {
            int fidx = best_i[p];
            const float* vp = g_vpix + (size_t)n * V * 3;
            int i0 = vi[fidx*3+0]*3, i1 = vi[fidx*3+1]*3, i2 = vi[fidx*3+2]*3;
            float X0 = vp[i0], Y0 = vp[i0+1], Z0 = vp[i0+2];
            float X1 = vp[i1], Y1 = vp[i1+1], Z1 = vp[i1+2];
            float X2 = vp[i2], Y2 = vp[i2+1], Z2 = vp[i2+2];
            float w0 = edge_fn(__fsub_rn(px,X1), __fsub_rn(Y2,Y1), __fsub_rn(py,Y1), __fsub_rn(X2,X1));
            float w1 = edge_fn(__fsub_rn(px,X2), __fsub_rn(Y0,Y2), __fsub_rn(py,Y2), __fsub_rn(X0,X2));
            float w2 = edge_fn(__fsub_rn(px,X0), __fsub_rn(Y1,Y0), __fsub_rn(py,Y0), __fsub_rn(X1,X0));
            float area = edge_fn(__fsub_rn(X2,X0), __fsub_rn(Y1,Y0), __fsub_rn(Y2,Y0), __fsub_rn(X1,X0));
            float sa = (fabsf(area) > EPSF) ? area : 1.0f;
            float b0 = __fdiv_rn(w0, sa), b1 = __fdiv_rn(w1, sa), b2 = __fdiv_rn(w2, sa);
            float bz0 = __fdiv_rn(b0, fmaxf(Z0, EPSF));
            float bz1 = __fdiv_rn(b1, fmaxf(Z1, EPSF));
            float bz2 = __fdiv_rn(b2, fmaxf(Z2, EPSF));
            float zis = fmaxf(__fadd_rn(__fadd_rn(bz0, bz1), bz2), EPSF);
            ba0 = __fdiv_rn(bz0, zis); ba1 = __fdiv_rn(bz1, zis); ba2 = __fdiv_rn(bz2, zis);
            depth = __fdiv_rn(1.0f, zis);

            int t0i = vti[fidx*3+0]*2, t1i = vti[fidx*3+1]*2, t2i = vti[fidx*3+2]*2;
            float u0 = vt[t0i], tv0 = __fsub_rn(1.0f, vt[t0i+1]);
            float u1 = vt[t1i], tv1 = __fsub_rn(1.0f, vt[t1i+1]);
            float u2 = vt[t2i], tv2 = __fsub_rn(1.0f, vt[t2i+1]);
            vtxv = __fadd_rn(__fadd_rn(__fmul_rn(ba0,u0), __fmul_rn(ba1,u1)), __fmul_rn(ba2,u2));
            vtyv = __fadd_rn(__fadd_rn(__fmul_rn(ba0,tv0), __fmul_rn(ba1,tv1)), __fmul_rn(ba2,tv2));

            float gx = __fsub_rn(__fmul_rn(vtxv, 2.0f), 1.0f);
            float gy = __fsub_rn(__fmul_rn(vtyv, 2.0f), 1.0f);
            float ix = __fsub_rn(__fmul_rn(__fmul_rn(__fadd_rn(gx,1.0f), 0.5f), (float)Wt), 0.5f);
            float iy = __fsub_rn(__fmul_rn(__fmul_rn(__fadd_rn(gy,1.0f), 0.5f), (float)Ht), 0.5f);
            float xf = floorf(ix), yf = floorf(iy);
            float fx = __fsub_rn(ix, xf), fy = __fsub_rn(iy, yf);
            int x0i = min(max((int)xf,     0), Wt - 1);
            int x1i = min(max((int)xf + 1, 0), Wt - 1);
            int y0i = min(max((int)yf,     0), Ht - 1);
            int y1i = min(max((int)yf + 1, 0), Ht - 1);
            float ofx = __fsub_rn(1.0f, fx), ofy = __fsub_rn(1.0f, fy);
            const float* tc = tex + (size_t)n * 3 * Ht * Wt;
            #pragma unroll
            for (int c = 0; c < 3; c++) {
                const float* tcc = tc + (size_t)c * Ht * Wt;
                float v00 = __ldg(tcc + (size_t)y0i * Wt + x0i);
                float v01 = __ldg(tcc + (size_t)y0i * Wt + x1i);
                float v10 = __ldg(tcc + (size_t)y1i * Wt + x0i);
                float v11 = __ldg(tcc + (size_t)y1i * Wt + x1i);
                float top = __fadd_rn(__fmul_rn(v00, ofx), __fmul_rn(v01, fx));
                float bot = __fadd_rn(__fmul_rn(v10, ofx), __fmul_rn(v11, fx));
                float rv  = __fadd_rn(__fmul_rn(top, ofy), __fmul_rn(bot, fy));
                if (c == 0) rc0 = rv; else if (c == 1) rc1 = rv; else rc2 = rv;
            }
        }

        out[((size_t)(n*3+0) * Hpix + hy) * Wpix + wx] = rc0;
        out[((size_t)(n*3+1) * Hpix + hy) * Wpix + wx] = rc1;
        out[((size_t)(n*3+2) * Hpix + hy) * Wpix + wx] = rc2;
        out[m_off + pix] = msk ? 1.0f : 0.0f;
        out[d_off + pix] = depth;
        out[v_off + pix*2 + 0] = vtxv;
        out[v_off + pix*2 + 1] = vtyv;
        out[b_off + ((size_t)(n*3+0) * Hpix + hy) * Wpix + wx] = ba0;
        out[b_off + ((size_t)(n*3+1) * Hpix + hy) * Wpix + wx] = ba1;
        out[b_off + ((size_t)(n*3+2) * Hpix + hy) * Wpix + wx] = ba2;
        out[i_off + pix] = (float)best_i[p];
    }
}

// ----------------------------------------------------------------
extern "C" void kernel_launch(void* const* d_in, const int* in_sizes, int n_in,
                              void* d_out, int out_size)
{
    const float* v       = (const float*)d_in[0];
    const float* tex     = (const float*)d_in[1];
    const float* vt      = (const float*)d_in[2];
    const int*   vi      = (const int*)  d_in[3];
    const int*   vti     = (const int*)  d_in[4];
    const float* campos  = (const float*)d_in[5];
    const float* camrot  = (const float*)d_in[6];
    const float* focal   = (const float*)d_in[7];
    const float* princpt = (const float*)d_in[8];

    int N = in_sizes[5] / 3;
    int V = in_sizes[0] / (3 * N);
    int F = in_sizes[3] / 3;
    int texPer = in_sizes[1] / (3 * N);
    int Wt = (int)(sqrt((double)texPer) + 0.5);
    int Ht = texPer / Wt;

    // reset sort state via memset nodes (no init kernel launch)
    void *p_hist, *p_cur, *p_zmin, *p_zmax;
    cudaGetSymbolAddress(&p_hist, g_hist);
    cudaGetSymbolAddress(&p_cur,  g_cursor);
    cudaGetSymbolAddress(&p_zmin, g_zmin);
    cudaGetSymbolAddress(&p_zmax, g_zmax);
    cudaMemsetAsync(p_hist, 0,    (size_t)N * NB * sizeof(int));
    cudaMemsetAsync(p_cur,  0,    (size_t)N * NB * sizeof(int));
    cudaMemsetAsync(p_zmin, 0xFF, (size_t)N * sizeof(unsigned));
    cudaMemsetAsync(p_zmax, 0x00, (size_t)N * sizeof(unsigned));

    project_kernel<<<(N * V + 255) / 256, 256>>>(v, campos, camrot, focal, princpt, N, V);
    setup_kernel<<<(N * F + 255) / 256, 256>>>(vi, N, V, F);
    scatter_kernel<<<(N * F + 255) / 256, 256>>>(N, F);
    dim3 grid(Wpix / TW, Hpix / TH, N);
    raster_kernel<<<grid, dim3(16, 16)>>>(vi, vti, vt, tex, (float*)d_out, N, V, F, Ht, Wt);
}